// round 17
// baseline (speedup 1.0000x reference)
#include <cuda_runtime.h>
#include <cuda_fp16.h>
#include <cstdint>

#define ROWSTRIDE 5248
#define NTILES    1312
#define GRIDSZ    148
#define NTHREADS  512
#define STAGE_BYTES 32768
#define NSTAGE    4
#define MB_OFF    131072u
#define SMEM_BYTES 131200

// Pre-converted W image: per s: 6 chunks x 16384 B (fp16, pre-swizzled)
#define WPRE_PER_S 98304
__device__ __align__(16) unsigned char g_wpre[41 * WPRE_PER_S];

static __device__ __forceinline__ uint32_t smem_u32(const void* p) {
    uint32_t a;
    asm("{ .reg .u64 t; cvta.to.shared.u64 t, %1; cvt.u32.u64 %0, t; }"
        : "=r"(a) : "l"(p));
    return a;
}
static __device__ __forceinline__ void ldsm4(uint32_t* r, uint32_t a) {
    asm volatile("ldmatrix.sync.aligned.m8n8.x4.shared.b16 {%0,%1,%2,%3}, [%4];"
                 : "=r"(r[0]), "=r"(r[1]), "=r"(r[2]), "=r"(r[3]) : "r"(a));
}
static __device__ __forceinline__ void ldsm4t(uint32_t* r, uint32_t a) {
    asm volatile("ldmatrix.sync.aligned.m8n8.x4.trans.shared.b16 {%0,%1,%2,%3}, [%4];"
                 : "=r"(r[0]), "=r"(r[1]), "=r"(r[2]), "=r"(r[3]) : "r"(a));
}
static __device__ __forceinline__ void mma_f16(float* c, const uint32_t* a, const uint32_t* b) {
    asm volatile("mma.sync.aligned.m16n8k16.row.col.f32.f16.f16.f32 "
                 "{%0,%1,%2,%3}, {%4,%5,%6,%7}, {%8,%9}, {%0,%1,%2,%3};"
                 : "+f"(c[0]), "+f"(c[1]), "+f"(c[2]), "+f"(c[3])
                 : "r"(a[0]), "r"(a[1]), "r"(a[2]), "r"(a[3]), "r"(b[0]), "r"(b[1]));
}
static __device__ __forceinline__ uint32_t cvt2h(float a, float b) {
    return (uint32_t)__half_as_ushort(__float2half_rn(a)) |
           ((uint32_t)__half_as_ushort(__float2half_rn(b)) << 16);
}
static __device__ __forceinline__ void cp16(uint32_t dst, const void* src) {
    asm volatile("cp.async.cg.shared.global [%0], [%1], 16;"
                 :: "r"(dst), "l"(src) : "memory");
}
static __device__ __forceinline__ void mbar_init(uint32_t a, uint32_t c) {
    asm volatile("mbarrier.init.shared.b64 [%0], %1;" :: "r"(a), "r"(c) : "memory");
}
static __device__ __forceinline__ void mbar_arrive(uint32_t a) {
    asm volatile("mbarrier.arrive.shared.b64 _, [%0];" :: "r"(a) : "memory");
}
static __device__ __forceinline__ void mbar_wait(uint32_t a, uint32_t par) {
    uint32_t done;
    asm volatile(
        "{\n\t.reg .pred p;\n\t"
        "mbarrier.try_wait.parity.acquire.cta.shared::cta.b64 p, [%1], %2;\n\t"
        "selp.b32 %0, 1, 0, p;\n\t}"
        : "=r"(done) : "r"(a), "r"(par) : "memory");
    if (!done) {
        asm volatile(
            "{\n\t.reg .pred P1;\n\t"
            "WL%=:\n\t"
            "mbarrier.try_wait.parity.acquire.cta.shared::cta.b64 P1, [%0], %1, 0x989680;\n\t"
            "@P1 bra.uni WD%=;\n\t"
            "bra.uni WL%=;\n\t"
            "WD%=:\n\t}"
            :: "r"(a), "r"(par) : "memory");
    }
}

// ------------- precompute: W fp32 -> swizzled fp16 image (6 x 16KB) ---------
__global__ void __launch_bounds__(256)
wsplit_kernel(const float* __restrict__ W) {
    const int step = gridDim.x * blockDim.x;
    const int TOT = 41 * 12288;                      // float4 count
    for (int v = blockIdx.x * blockDim.x + threadIdx.x; v < TOT; v += step) {
        const int s = v / 12288, rem = v % 12288;
        const int k = rem >> 5, q = rem & 31;        // k 0..383, q = float4-in-row
        const float4 w = *(const float4*)(W + (size_t)v * 4);
        const int c = k >> 6, kr = k & 63;           // 6 chunks of 64 k-rows
        const size_t d = (size_t)s * WPRE_PER_S + (size_t)c * 16384
                       + (size_t)kr * 256
                       + ((((uint32_t)(q >> 1)) ^ ((uint32_t)kr & 7u)) << 4)
                       + (uint32_t)((q & 1) << 3);
        *(uint2*)(g_wpre + d) = make_uint2(cvt2h(w.x, w.y), cvt2h(w.z, w.w));
    }
}

// ------------------------------ main kernel --------------------------------
__global__ void __launch_bounds__(NTHREADS, 1)
poslin_kernel(const float* __restrict__ x,
              const float* __restrict__ bias, float* __restrict__ out)
{
    extern __shared__ __align__(128) char smem[];
    const uint32_t sb = smem_u32(smem);
    const int tid  = threadIdx.x;
    const int lane = tid & 31;
    const int wid  = tid >> 5;                 // 0..15

    const uint32_t mbF = sb + MB_OFF;          // full[4] at +0, empty[4] at +32
    const uint32_t mbE = sb + MB_OFF + 32u;

    if (tid == 0) {
        _Pragma("unroll")
        for (int r = 0; r < NSTAGE; ++r) {
            mbar_init(mbF + 8u * r, 256);      // producer threads
            mbar_init(mbE + 8u * r, 256);      // consumer threads
        }
    }
    __syncthreads();

    const int start = (int)(((long)blockIdx.x * NTILES) / GRIDSZ);
    const int end   = (int)(((long)(blockIdx.x + 1) * NTILES) / GRIDSZ);
    const int Ctot  = (end - start) * 6;       // 6 K64-chunks per tile

    if (wid < 8) {
        // ============ PRODUCER (8 warps, 256 thr): 4-stage ring =============
        const int ptid = tid;                        // 0..255
        const int xq = ptid & 15, xr0 = ptid >> 4;   // f4-in-row (0..15), row base 0..15
        const uint32_t xCvt = ((((uint32_t)(xq >> 1)) ^ ((uint32_t)xr0 & 7u)) << 4)
                            + (uint32_t)((xq & 1) << 3);

        int tL = start, cL = 0;
        int r = 0; uint32_t pph = 1;           // producer phase starts 1

        for (int g = 0; g < Ctot; ++g) {
            mbar_wait(mbE + 8u * r, pph);
            const uint32_t so = (uint32_t)r * STAGE_BYTES;
            const int s_ = tL >> 5, mt_ = tL & 31, bb_ = mt_ << 7;
            const int e_ = (s_ - 1) * 128 + cL * 64 + xq * 4;
            const bool v_ = (e_ >= 0) && (e_ < ROWSTRIDE);
            // W fp16 16KB pre-swizzled: 4 x 16B per thread
            {
                const unsigned char* wsrc = g_wpre + (size_t)s_ * WPRE_PER_S
                                          + (size_t)cL * 16384 + (size_t)ptid * 16;
                const uint32_t wdst = sb + so + 16384u + (uint32_t)ptid * 16u;
                _Pragma("unroll")
                for (int i = 0; i < 4; ++i)
                    cp16(wdst + (uint32_t)(i * 4096), wsrc + (size_t)i * 4096);
                asm volatile("cp.async.commit_group;" ::: "memory");
            }
            // x: 8 float4 LDG, fp16 cvt + STS (16KB tile, 128B pitch)
            float4 xa[8];
            _Pragma("unroll")
            for (int it = 0; it < 8; ++it)
                xa[it] = v_ ? *(const float4*)(x + (size_t)(bb_ + xr0 + 16*it) * ROWSTRIDE + e_)
                            : make_float4(0.f, 0.f, 0.f, 0.f);
            _Pragma("unroll")
            for (int it = 0; it < 8; ++it) {
                uint32_t o_ = so + (uint32_t)(xr0 + 16*it) * 128u + xCvt;
                *(uint2*)(smem + o_) = make_uint2(cvt2h(xa[it].x, xa[it].y),
                                                  cvt2h(xa[it].z, xa[it].w));
            }
            asm volatile("cp.async.wait_group 0;" ::: "memory");
            mbar_arrive(mbF + 8u * r);
            if (++r == NSTAGE) { r = 0; pph ^= 1u; }
            if (++cL == 6) { cL = 0; ++tL; }
        }
    } else {
        // ========== CONSUMER (8 warps, 256 thr): 64x32 warp tile ============
        const int cwid = wid - 8;
        const int m0 = (cwid >> 2) << 6;       // 0, 64
        const int n0 = (cwid & 3) << 5;        // 0, 32, 64, 96
        const int g8 = lane >> 2, tig = lane & 3;

        const uint32_t aRowB = (uint32_t)(m0 + (lane & 15));
        const uint32_t aKC   = (uint32_t)(lane >> 4);
        const uint32_t l7    = (uint32_t)(lane & 7);
        const uint32_t bKrB  = (uint32_t)(lane & 15);
        const uint32_t bNCB  = (uint32_t)((n0 >> 3) + (lane >> 4));

        int t = start, c = 0;
        int r = 0; uint32_t cph = 0;           // consumer phase starts 0
        float acc[4][4][4];

        for (int g = 0; g < Ctot; ++g) {
            mbar_wait(mbF + 8u * r, cph);
            if (c == 0) {
                _Pragma("unroll")
                for (int i = 0; i < 4; ++i)
                    _Pragma("unroll")
                    for (int j = 0; j < 4; ++j)
                        _Pragma("unroll")
                        for (int u = 0; u < 4; ++u) acc[i][j][u] = 0.f;
            }
            {
                const uint32_t Ab = sb + (uint32_t)r * STAGE_BYTES;
                _Pragma("unroll")
                for (int ks = 0; ks < 4; ++ks) {
                    uint32_t ah[4][4];
                    _Pragma("unroll")
                    for (int i = 0; i < 4; ++i) {
                        uint32_t ad = Ab + (aRowB + 16u*i) * 128u
                                    + ((((uint32_t)(ks * 2) + aKC) ^ l7) << 4);
                        ldsm4(ah[i], ad);
                    }
                    _Pragma("unroll")
                    for (int jj = 0; jj < 2; ++jj) {
                        uint32_t bd = Ab + 16384u + (bKrB + 16u*ks) * 256u
                                    + (((bNCB + 2u*jj) ^ l7) << 4);
                        uint32_t bh_[4];
                        ldsm4t(bh_, bd);
                        _Pragma("unroll")
                        for (int i = 0; i < 4; ++i) {
                            mma_f16(acc[i][2*jj],     ah[i], bh_);
                            mma_f16(acc[i][2*jj + 1], ah[i], bh_ + 2);
                        }
                    }
                }
            }
            mbar_arrive(mbE + 8u * r);
            if (++r == NSTAGE) { r = 0; cph ^= 1u; }
            if (c == 5) {
                const int s = t >> 5, bbase = (t & 31) << 7;
                const float* brow = bias + s * 128;
                _Pragma("unroll")
                for (int j = 0; j < 4; ++j) {
                    const int n = n0 + 8 * j + 2 * tig;
                    const float b0 = brow[n], b1 = brow[n + 1];
                    _Pragma("unroll")
                    for (int i = 0; i < 4; ++i) {
                        float* rp = out + (size_t)(bbase + m0 + 16 * i + g8) * ROWSTRIDE
                                  + (size_t)s * 128 + n;
                        float2 v0, v1;
                        v0.x = fmaxf(acc[i][j][0] + b0, 0.f);
                        v0.y = fmaxf(acc[i][j][1] + b1, 0.f);
                        v1.x = fmaxf(acc[i][j][2] + b0, 0.f);
                        v1.y = fmaxf(acc[i][j][3] + b1, 0.f);
                        __stcs((float2*)rp, v0);
                        __stcs((float2*)(rp + 8 * ROWSTRIDE), v1);
                    }
                }
            }
            if (++c == 6) { c = 0; ++t; }
        }
    }
}

extern "C" void kernel_launch(void* const* d_in, const int* in_sizes, int n_in,
                              void* d_out, int out_size) {
    const float* x = (const float*)d_in[0];
    const float* W = (const float*)d_in[1];
    const float* b = (const float*)d_in[2];
    float* out = (float*)d_out;
    wsplit_kernel<<<296, 256>>>(W);
    cudaFuncSetAttribute(poslin_kernel,
                         cudaFuncAttributeMaxDynamicSharedMemorySize, SMEM_BYTES);
    poslin_kernel<<<GRIDSZ, NTHREADS, SMEM_BYTES>>>(x, b, out);
}